// round 6
// baseline (speedup 1.0000x reference)
#include <cuda_runtime.h>
#include <cuda_bf16.h>
#include <math.h>

// Problem constants
#define BB 4
#define SS 2048
#define HH 16
#define DMODEL 1024
#define DK 64
#define MM (BB*SS)            // 8192

// ---------------- scratch (static device allocations are allowed) ----------
__device__ float g_q[BB*HH*SS*DK];     // [B,H,S,Dk]
__device__ float g_k[BB*HH*SS*DK];
__device__ float g_v[BB*HH*SS*DK];
__device__ float g_attn[BB*SS*DMODEL]; // [B,S,D]

// ============================================================================
// GEMM: C = A @ W^T + bias.  A:[M=8192,K=1024] row-major, W:[N=1024,K=1024]
// row-major. split=1 -> scatter to [B,H,S,Dk]; split=0 -> plain [M,N].
// BM=BN=128, BK=16, 256 threads, 8x8 microtile.
// ============================================================================
#define GBM 128
#define GBN 128
#define GBK 16
#define GLDA 132   // padded row length (words) for As/Ws: conflict-tamed

__global__ __launch_bounds__(256)
void gemm_bias_kernel(const float* __restrict__ A,
                      const float* __restrict__ W,
                      const float* __restrict__ bias,
                      float* __restrict__ C,
                      int split)
{
    __shared__ float As[GBK][GLDA];
    __shared__ float Ws[GBK][GLDA];

    const int tid = threadIdx.x;
    const int tx  = tid & 15;     // 0..15 -> N fragment
    const int ty  = tid >> 4;     // 0..15 -> M fragment
    const int m0  = blockIdx.y * GBM;
    const int n0  = blockIdx.x * GBN;

    const int lrow = tid >> 2;    // 0..63
    const int lkq  = tid & 3;     // 0..3 (k-quad)

    float acc[8][8];
#pragma unroll
    for (int i = 0; i < 8; i++)
#pragma unroll
        for (int j = 0; j < 8; j++) acc[i][j] = 0.f;

    for (int k0 = 0; k0 < DMODEL; k0 += GBK) {
#pragma unroll
        for (int p = 0; p < 2; p++) {
            const int r = lrow + p * 64;
            float4 av = *(const float4*)(A + (size_t)(m0 + r) * DMODEL + k0 + lkq * 4);
            As[lkq*4+0][r] = av.x;  As[lkq*4+1][r] = av.y;
            As[lkq*4+2][r] = av.z;  As[lkq*4+3][r] = av.w;
            float4 wv = *(const float4*)(W + (size_t)(n0 + r) * DMODEL + k0 + lkq * 4);
            Ws[lkq*4+0][r] = wv.x;  Ws[lkq*4+1][r] = wv.y;
            Ws[lkq*4+2][r] = wv.z;  Ws[lkq*4+3][r] = wv.w;
        }
        __syncthreads();

#pragma unroll
        for (int k = 0; k < GBK; k++) {
            float a[8], b[8];
#pragma unroll
            for (int i = 0; i < 8; i++) a[i] = As[k][i * 16 + ty];
#pragma unroll
            for (int j = 0; j < 8; j++) b[j] = Ws[k][j * 16 + tx];
#pragma unroll
            for (int i = 0; i < 8; i++)
#pragma unroll
                for (int j = 0; j < 8; j++)
                    acc[i][j] = fmaf(a[i], b[j], acc[i][j]);
        }
        __syncthreads();
    }

    // epilogue: + bias, scatter
#pragma unroll
    for (int i = 0; i < 8; i++) {
        const int m  = m0 + i * 16 + ty;
        const int b_ = m >> 11;          // / S (2048)
        const int s  = m & (SS - 1);
#pragma unroll
        for (int j = 0; j < 8; j++) {
            const int n = n0 + j * 16 + tx;
            const float v = acc[i][j] + bias[n];
            if (split) {
                const int h = n >> 6;    // / Dk
                const int d = n & (DK - 1);
                C[(((size_t)(b_ * HH + h) * SS + s) << 6) + d] = v;
            } else {
                C[(size_t)m * DMODEL + n] = v;
            }
        }
    }
}

// ============================================================================
// Flash attention (causal). One block = 64 query rows of one (b,h).
// grid = (S/64, B*H), 128 threads. Microtile: 4 rows x 8 cols per thread,
// interleaved mapping (rows i*16+ty, cols j*8+tx) => conflict-free smem reads
// with +1 padded rows. Online softmax; upper-triangular KV tiles skipped.
// ============================================================================
#define FBM 64
#define FBN 64
#define FPAD 65
#define FLASH_SMEM (4 * FBM * FPAD * (int)sizeof(float))   // 66560 B

__global__ __launch_bounds__(128)
void flash_kernel(const float* __restrict__ gq,
                  const float* __restrict__ gk,
                  const float* __restrict__ gv,
                  float* __restrict__ gout)
{
    extern __shared__ float sm[];
    float* Qs = sm;                   // [64][65]
    float* Ks = Qs + FBM * FPAD;
    float* Vs = Ks + FBM * FPAD;
    float* Ps = Vs + FBM * FPAD;

    const int tid = threadIdx.x;
    const int tx  = tid & 7;          // 0..7
    const int ty  = tid >> 3;         // 0..15
    const int bx  = blockIdx.x;       // query tile index
    const int bh  = blockIdx.y;       // b*H + h
    const int q0  = bx * FBM;
    const size_t base = (size_t)bh * SS * DK;

    // load Q tile (pre-scaled by 1/sqrt(Dk) = 0.125)
    {
        const float* qptr = gq + base + (size_t)q0 * DK;
        for (int t = tid; t < FBM * 16; t += 128) {
            const int r = t >> 4, c = (t & 15) * 4;
            float4 v = *(const float4*)(qptr + r * DK + c);
            Qs[r * FPAD + c + 0] = v.x * 0.125f;
            Qs[r * FPAD + c + 1] = v.y * 0.125f;
            Qs[r * FPAD + c + 2] = v.z * 0.125f;
            Qs[r * FPAD + c + 3] = v.w * 0.125f;
        }
    }

    float m_i[4], l_i[4], acc[4][8];
#pragma unroll
    for (int i = 0; i < 4; i++) {
        m_i[i] = -INFINITY; l_i[i] = 0.f;
#pragma unroll
        for (int j = 0; j < 8; j++) acc[i][j] = 0.f;
    }

    for (int kt = 0; kt <= bx; kt++) {
        const int k0 = kt * FBN;
        __syncthreads();   // prev iter done with Ks/Vs/Ps; also fences Q fill
        {
            const float* kptr = gk + base + (size_t)k0 * DK;
            const float* vptr = gv + base + (size_t)k0 * DK;
            for (int t = tid; t < FBN * 16; t += 128) {
                const int r = t >> 4, c = (t & 15) * 4;
                float4 kv = *(const float4*)(kptr + r * DK + c);
                Ks[r*FPAD+c+0]=kv.x; Ks[r*FPAD+c+1]=kv.y;
                Ks[r*FPAD+c+2]=kv.z; Ks[r*FPAD+c+3]=kv.w;
                float4 vv = *(const float4*)(vptr + r * DK + c);
                Vs[r*FPAD+c+0]=vv.x; Vs[r*FPAD+c+1]=vv.y;
                Vs[r*FPAD+c+2]=vv.z; Vs[r*FPAD+c+3]=vv.w;
            }
        }
        __syncthreads();

        // scores S = Q K^T (Q already scaled)
        float s[4][8];
#pragma unroll
        for (int i = 0; i < 4; i++)
#pragma unroll
            for (int j = 0; j < 8; j++) s[i][j] = 0.f;

#pragma unroll 4
        for (int d = 0; d < DK; d++) {
            float qf[4], kf[8];
#pragma unroll
            for (int i = 0; i < 4; i++) qf[i] = Qs[(i * 16 + ty) * FPAD + d];
#pragma unroll
            for (int j = 0; j < 8; j++) kf[j] = Ks[(j * 8 + tx) * FPAD + d];
#pragma unroll
            for (int i = 0; i < 4; i++)
#pragma unroll
                for (int j = 0; j < 8; j++)
                    s[i][j] = fmaf(qf[i], kf[j], s[i][j]);
        }

        // causal mask: only the diagonal tile needs it
        if (kt == bx) {
#pragma unroll
            for (int i = 0; i < 4; i++) {
                const int qr = q0 + i * 16 + ty;
#pragma unroll
                for (int j = 0; j < 8; j++) {
                    const int kc = k0 + j * 8 + tx;
                    if (kc > qr) s[i][j] = -INFINITY;
                }
            }
        }

        // online softmax update (row = 8 lanes share: shfl over xor 1,2,4)
#pragma unroll
        for (int i = 0; i < 4; i++) {
            float mx = s[i][0];
#pragma unroll
            for (int j = 1; j < 8; j++) mx = fmaxf(mx, s[i][j]);
            mx = fmaxf(mx, __shfl_xor_sync(0xffffffffu, mx, 1));
            mx = fmaxf(mx, __shfl_xor_sync(0xffffffffu, mx, 2));
            mx = fmaxf(mx, __shfl_xor_sync(0xffffffffu, mx, 4));
            const float m_new = fmaxf(m_i[i], mx);
            const float scale = __expf(m_i[i] - m_new);
            float ps = 0.f;
#pragma unroll
            for (int j = 0; j < 8; j++) {
                const float p = __expf(s[i][j] - m_new);
                s[i][j] = p;
                ps += p;
            }
            ps += __shfl_xor_sync(0xffffffffu, ps, 1);
            ps += __shfl_xor_sync(0xffffffffu, ps, 2);
            ps += __shfl_xor_sync(0xffffffffu, ps, 4);
            l_i[i] = l_i[i] * scale + ps;
            m_i[i] = m_new;
#pragma unroll
            for (int j = 0; j < 8; j++) acc[i][j] *= scale;
        }

        // stage P
#pragma unroll
        for (int i = 0; i < 4; i++)
#pragma unroll
            for (int j = 0; j < 8; j++)
                Ps[(i * 16 + ty) * FPAD + (j * 8 + tx)] = s[i][j];
        __syncthreads();

        // acc += P @ V
#pragma unroll 4
        for (int kk = 0; kk < FBN; kk++) {
            float pf[4], vf[8];
#pragma unroll
            for (int i = 0; i < 4; i++) pf[i] = Ps[(i * 16 + ty) * FPAD + kk];
#pragma unroll
            for (int j = 0; j < 8; j++) vf[j] = Vs[kk * FPAD + j * 8 + tx];
#pragma unroll
            for (int i = 0; i < 4; i++)
#pragma unroll
                for (int j = 0; j < 8; j++)
                    acc[i][j] = fmaf(pf[i], vf[j], acc[i][j]);
        }
    }

    // epilogue: normalize and write [B,S,D] (D index = h*64 + d)
    const int b_ = bh >> 4;
    const int h  = bh & (HH - 1);
#pragma unroll
    for (int i = 0; i < 4; i++) {
        const float inv = 1.0f / l_i[i];
        const int srow = q0 + i * 16 + ty;
        float* op = gout + ((size_t)(b_ * SS + srow)) * DMODEL + h * DK;
#pragma unroll
        for (int j = 0; j < 8; j++)
            op[j * 8 + tx] = acc[i][j] * inv;
    }
}

// ============================================================================
// launch
// ============================================================================
extern "C" void kernel_launch(void* const* d_in, const int* in_sizes, int n_in,
                              void* d_out, int out_size)
{
    const float* Q   = (const float*)d_in[0];
    const float* K   = (const float*)d_in[1];
    const float* V   = (const float*)d_in[2];
    // d_in[3] = mask (causal tril; handled analytically)
    const float* W_q = (const float*)d_in[4];
    const float* b_q = (const float*)d_in[5];
    const float* W_k = (const float*)d_in[6];
    const float* b_k = (const float*)d_in[7];
    const float* W_v = (const float*)d_in[8];
    const float* b_v = (const float*)d_in[9];
    const float* W_o = (const float*)d_in[10];
    const float* b_o = (const float*)d_in[11];
    float* out = (float*)d_out;

    float *gq, *gk, *gv, *gattn;
    cudaGetSymbolAddress((void**)&gq,    g_q);
    cudaGetSymbolAddress((void**)&gk,    g_k);
    cudaGetSymbolAddress((void**)&gv,    g_v);
    cudaGetSymbolAddress((void**)&gattn, g_attn);

    cudaFuncSetAttribute(flash_kernel,
                         cudaFuncAttributeMaxDynamicSharedMemorySize,
                         FLASH_SMEM);

    dim3 ggrid(DMODEL / GBN, MM / GBM);   // (8, 64)

    gemm_bias_kernel<<<ggrid, 256>>>(Q, W_q, b_q, gq, 1);
    gemm_bias_kernel<<<ggrid, 256>>>(K, W_k, b_k, gk, 1);
    gemm_bias_kernel<<<ggrid, 256>>>(V, W_v, b_v, gv, 1);

    flash_kernel<<<dim3(SS / FBM, BB * HH), 128, FLASH_SMEM>>>(gq, gk, gv, gattn);

    gemm_bias_kernel<<<ggrid, 256>>>(gattn, W_o, b_o, out, 0);
}

// round 8
// speedup vs baseline: 2.2141x; 2.2141x over previous
#include <cuda_runtime.h>
#include <cuda_fp16.h>
#include <math.h>
#include <stdint.h>

// Problem constants
#define BB 4
#define SS 2048
#define HH 16
#define DMODEL 1024
#define DK 64
#define MM (BB*SS)            // 8192

// ---------------- scratch (__device__ globals: allocation-guard safe) ------
__device__ float  g_q[(size_t)MM*DMODEL];      // [B,S,D] fp32
__device__ float  g_k[(size_t)MM*DMODEL];
__device__ float  g_v[(size_t)MM*DMODEL];
__device__ __half g_attn[(size_t)MM*DMODEL];   // [B,S,D] fp16 (O-proj input)
__device__ __half g_hq[(size_t)MM*DMODEL];     // fp16 copies of inputs
__device__ __half g_hk[(size_t)MM*DMODEL];
__device__ __half g_hv[(size_t)MM*DMODEL];
__device__ __half g_hw[(size_t)4*DMODEL*DMODEL]; // Wq,Wk,Wv,Wo fp16

// ============================================================================
// PTX helpers — ONLY plain-ISA instructions (sm_80-era): cp.async, ldmatrix,
// mma.sync. NO tcgen05 (harness PTX target lacks the 'a' suffix).
// ============================================================================
__device__ __forceinline__ uint32_t s2u(const void* p) {
    uint32_t a;
    asm("{ .reg .u64 t; cvta.to.shared.u64 t, %1; cvt.u32.u64 %0, t; }"
        : "=r"(a) : "l"(p));
    return a;
}

__device__ __forceinline__ void cp16(uint32_t dst, const void* src) {
    asm volatile("cp.async.cg.shared.global [%0], [%1], 16;"
                 :: "r"(dst), "l"(src));
}
__device__ __forceinline__ void cp_commit() {
    asm volatile("cp.async.commit_group;");
}
__device__ __forceinline__ void cp_wait1() {
    asm volatile("cp.async.wait_group 1;" ::: "memory");
}
__device__ __forceinline__ void cp_wait0() {
    asm volatile("cp.async.wait_group 0;" ::: "memory");
}

__device__ __forceinline__ void ldsm4(uint32_t* r, uint32_t a) {
    asm volatile("ldmatrix.sync.aligned.m8n8.x4.shared.b16 {%0,%1,%2,%3}, [%4];"
                 : "=r"(r[0]), "=r"(r[1]), "=r"(r[2]), "=r"(r[3]) : "r"(a));
}

__device__ __forceinline__ void mma16816(float* d, const uint32_t* a,
                                         uint32_t b0, uint32_t b1) {
    asm volatile(
        "mma.sync.aligned.m16n8k16.row.col.f32.f16.f16.f32 "
        "{%0,%1,%2,%3}, {%4,%5,%6,%7}, {%8,%9}, {%0,%1,%2,%3};"
        : "+f"(d[0]), "+f"(d[1]), "+f"(d[2]), "+f"(d[3])
        : "r"(a[0]), "r"(a[1]), "r"(a[2]), "r"(a[3]), "r"(b0), "r"(b1));
}

// ============================================================================
// fp32 -> fp16 conversion (vectorized, n % 4 == 0)
// ============================================================================
__global__ __launch_bounds__(256)
void f2h_kernel(const float* __restrict__ src, __half* __restrict__ dst, int n)
{
    int i = (blockIdx.x * blockDim.x + threadIdx.x) << 2;
    if (i >= n) return;
    float4 v = *(const float4*)(src + i);
    __half2* d = (__half2*)(dst + i);
    d[0] = __floats2half2_rn(v.x, v.y);
    d[1] = __floats2half2_rn(v.z, v.w);
}

// ============================================================================
// HMMA GEMM: C[M,1024](fp32) = A[M,1024](fp16) @ W[1024,1024](fp16)^T + bias
// CTA tile 128x128, K-step 32, 256 thr = 8 warps (2M x 4N), warp tile 64x32.
// Double-buffered smem via cp.async; padded pitch 40 halves (80B) gives
// conflict-free ldmatrix for both operands (row.col, no .trans).
// grid = (1024/128, M/128) = (8, 64).
// ============================================================================
#define GP 40            // smem pitch in halves (80 B): banks 0,20,8,28,16,4,24,12
#define GTILE (128*GP)   // halves per tile buffer (10240 B)

__global__ __launch_bounds__(256)
void gemm_hmma(const __half* __restrict__ A,
               const __half* __restrict__ W,
               const float* __restrict__ bias,
               float* __restrict__ C)
{
    __shared__ __half As[2][GTILE];
    __shared__ __half Bs[2][GTILE];

    const int tid   = threadIdx.x;
    const int wid   = tid >> 5;
    const int lane  = tid & 31;
    const int warpM = wid >> 2;        // 0..1
    const int warpN = wid & 3;         // 0..3
    const int m0 = blockIdx.y * 128;
    const int n0 = blockIdx.x * 128;

    const uint32_t sA = s2u(As);
    const uint32_t sB = s2u(Bs);

    float acc[4][4][4];
#pragma unroll
    for (int i = 0; i < 4; i++)
#pragma unroll
        for (int j = 0; j < 4; j++)
#pragma unroll
            for (int k = 0; k < 4; k++) acc[i][j][k] = 0.f;

    // loader: 512 16B-chunks per operand per step; 2 per thread
    const int lr0 = tid >> 2;          // row for chunk tid
    const int lc0 = tid & 3;           // 16B-chunk within row

#define ISSUE_LOADS(buf, k0)                                                   \
    {                                                                          \
        _Pragma("unroll")                                                      \
        for (int it = 0; it < 2; ++it) {                                       \
            const int r  = lr0 + it * 64;                                      \
            const uint32_t so = (uint32_t)(r * 80 + lc0 * 16);                 \
            cp16(sA + (buf) * (GTILE * 2) + so,                                \
                 A + (size_t)(m0 + r) * DMODEL + (k0) + lc0 * 8);              \
            cp16(sB + (buf) * (GTILE * 2) + so,                                \
                 W + (size_t)(n0 + r) * DMODEL + (k0) + lc0 * 8);              \
        }                                                                      \
        cp_commit();                                                           \
    }

    ISSUE_LOADS(0, 0);

    // ldmatrix lane-address components (loop-invariant)
    const int a_row_in  = (lane & 15);            // row within 16-row frag
    const int a_k8      = (lane >> 4) << 4;       // 0 or 16 bytes (k8 select)
    const int b_nsub    = (lane & 7) + ((lane >> 4) & 1) * 8;
    const int b_k8      = ((lane >> 3) & 1) << 4;

    for (int s = 0; s < 32; ++s) {
        if (s + 1 < 32) { ISSUE_LOADS((s + 1) & 1, (s + 1) * 32); cp_wait1(); }
        else            { cp_wait0(); }
        __syncthreads();

        const uint32_t a_base = sA + (uint32_t)(s & 1) * (GTILE * 2);
        const uint32_t b_base = sB + (uint32_t)(s & 1) * (GTILE * 2);

#pragma unroll
        for (int kk = 0; kk < 2; ++kk) {
            uint32_t ar[4][4];
#pragma unroll
            for (int mf = 0; mf < 4; ++mf) {
                const int row = warpM * 64 + mf * 16 + a_row_in;
                ldsm4(ar[mf], a_base + (uint32_t)(row * 80 + kk * 32 + a_k8));
            }
            uint32_t br[2][4];
#pragma unroll
            for (int nf2 = 0; nf2 < 2; ++nf2) {
                const int nrow = warpN * 32 + nf2 * 16 + b_nsub;
                ldsm4(br[nf2], b_base + (uint32_t)(nrow * 80 + kk * 32 + b_k8));
            }
#pragma unroll
            for (int mf = 0; mf < 4; ++mf)
#pragma unroll
                for (int nf = 0; nf < 4; ++nf)
                    mma16816(acc[mf][nf], ar[mf],
                             br[nf >> 1][(nf & 1) * 2],
                             br[nf >> 1][(nf & 1) * 2 + 1]);
        }
        __syncthreads();
    }

    // epilogue: + bias, fp32 out
    const int rb = m0 + warpM * 64 + (lane >> 2);
    const int cb = n0 + warpN * 32 + (lane & 3) * 2;
#pragma unroll
    for (int nf = 0; nf < 4; ++nf) {
        const int c = cb + nf * 8;
        const float b0 = __ldg(bias + c), b1 = __ldg(bias + c + 1);
#pragma unroll
        for (int mf = 0; mf < 4; ++mf) {
            const int r = rb + mf * 16;
            float2 v0 = make_float2(acc[mf][nf][0] + b0, acc[mf][nf][1] + b1);
            float2 v1 = make_float2(acc[mf][nf][2] + b0, acc[mf][nf][3] + b1);
            *(float2*)(C + (size_t)r * DMODEL + c)       = v0;
            *(float2*)(C + (size_t)(r + 8) * DMODEL + c) = v1;
        }
    }
#undef ISSUE_LOADS
}

// ============================================================================
// Flash attention (causal), fp32 SIMT (unchanged from passing version).
// q/k/v in [B,S,D] fp32 (head h at column h*64). Output [B,S,D] fp16.
// grid=(S/64, B*H), 128 threads.
// ============================================================================
#define FBM 64
#define FBN 64
#define FPAD 65
#define FLASH_SMEM (4 * FBM * FPAD * (int)sizeof(float))   // 66560 B

__global__ __launch_bounds__(128)
void flash_kernel(const float* __restrict__ gq,
                  const float* __restrict__ gk,
                  const float* __restrict__ gv,
                  __half* __restrict__ gout)
{
    extern __shared__ float sm[];
    float* Qs = sm;                   // [64][65]
    float* Ks = Qs + FBM * FPAD;
    float* Vs = Ks + FBM * FPAD;
    float* Ps = Vs + FBM * FPAD;

    const int tid = threadIdx.x;
    const int tx  = tid & 7;
    const int ty  = tid >> 3;
    const int bx  = blockIdx.x;
    const int bh  = blockIdx.y;
    const int q0  = bx * FBM;
    const int b_  = bh >> 4;
    const int h   = bh & (HH - 1);
    const size_t rowbase = (size_t)b_ * SS;
    const int    coloff  = h * DK;

    {
        const float* qptr = gq + (rowbase + q0) * DMODEL + coloff;
        for (int t = tid; t < FBM * 16; t += 128) {
            const int r = t >> 4, c = (t & 15) * 4;
            float4 v = *(const float4*)(qptr + (size_t)r * DMODEL + c);
            Qs[r * FPAD + c + 0] = v.x * 0.125f;
            Qs[r * FPAD + c + 1] = v.y * 0.125f;
            Qs[r * FPAD + c + 2] = v.z * 0.125f;
            Qs[r * FPAD + c + 3] = v.w * 0.125f;
        }
    }

    float m_i[4], l_i[4], acc[4][8];
#pragma unroll
    for (int i = 0; i < 4; i++) {
        m_i[i] = -INFINITY; l_i[i] = 0.f;
#pragma unroll
        for (int j = 0; j < 8; j++) acc[i][j] = 0.f;
    }

    for (int kt = 0; kt <= bx; kt++) {
        const int k0 = kt * FBN;
        __syncthreads();
        {
            const float* kptr = gk + (rowbase + k0) * DMODEL + coloff;
            const float* vptr = gv + (rowbase + k0) * DMODEL + coloff;
            for (int t = tid; t < FBN * 16; t += 128) {
                const int r = t >> 4, c = (t & 15) * 4;
                float4 kv = *(const float4*)(kptr + (size_t)r * DMODEL + c);
                Ks[r*FPAD+c+0]=kv.x; Ks[r*FPAD+c+1]=kv.y;
                Ks[r*FPAD+c+2]=kv.z; Ks[r*FPAD+c+3]=kv.w;
                float4 vv = *(const float4*)(vptr + (size_t)r * DMODEL + c);
                Vs[r*FPAD+c+0]=vv.x; Vs[r*FPAD+c+1]=vv.y;
                Vs[r*FPAD+c+2]=vv.z; Vs[r*FPAD+c+3]=vv.w;
            }
        }
        __syncthreads();

        float s[4][8];
#pragma unroll
        for (int i = 0; i < 4; i++)
#pragma unroll
            for (int j = 0; j < 8; j++) s[i][j] = 0.f;

#pragma unroll 4
        for (int d = 0; d < DK; d++) {
            float qf[4], kf[8];
#pragma unroll
            for (int i = 0; i < 4; i++) qf[i] = Qs[(i * 16 + ty) * FPAD + d];
#pragma unroll
            for (int j = 0; j < 8; j++) kf[j] = Ks[(j * 8 + tx) * FPAD + d];
#pragma unroll
            for (int i = 0; i < 4; i++)
#pragma unroll
                for (int j = 0; j < 8; j++)
                    s[i][j] = fmaf(qf[i], kf[j], s[i][j]);
        }

        if (kt == bx) {
#pragma unroll
            for (int i = 0; i < 4; i++) {
                const int qr = q0 + i * 16 + ty;
#pragma unroll
                for (int j = 0; j < 8; j++) {
                    const int kc = k0 + j * 8 + tx;
                    if (kc > qr) s[i][j] = -INFINITY;
                }
            }
        }

#pragma unroll
        for (int i = 0; i < 4; i++) {
            float mx = s[i][0];
#pragma unroll
            for (int j = 1; j < 8; j++) mx = fmaxf(mx, s[i][j]);
            mx = fmaxf(mx, __shfl_xor_sync(0xffffffffu, mx, 1));
            mx = fmaxf(mx, __shfl_xor_sync(0xffffffffu, mx, 2));
            mx = fmaxf(mx, __shfl_xor_sync(0xffffffffu, mx, 4));
            const float m_new = fmaxf(m_i[i], mx);
            const float scale = __expf(m_i[i] - m_new);
            float ps = 0.f;
#pragma unroll
            for (int j = 0; j < 8; j++) {
                const float p = __expf(s[i][j] - m_new);
                s[i][j] = p;
                ps += p;
            }
            ps += __shfl_xor_sync(0xffffffffu, ps, 1);
            ps += __shfl_xor_sync(0xffffffffu, ps, 2);
            ps += __shfl_xor_sync(0xffffffffu, ps, 4);
            l_i[i] = l_i[i] * scale + ps;
            m_i[i] = m_new;
#pragma unroll
            for (int j = 0; j < 8; j++) acc[i][j] *= scale;
        }

#pragma unroll
        for (int i = 0; i < 4; i++)
#pragma unroll
            for (int j = 0; j < 8; j++)
                Ps[(i * 16 + ty) * FPAD + (j * 8 + tx)] = s[i][j];
        __syncthreads();

#pragma unroll 4
        for (int kk = 0; kk < FBN; kk++) {
            float pf[4], vf[8];
#pragma unroll
            for (int i = 0; i < 4; i++) pf[i] = Ps[(i * 16 + ty) * FPAD + kk];
#pragma unroll
            for (int j = 0; j < 8; j++) vf[j] = Vs[kk * FPAD + j * 8 + tx];
#pragma unroll
            for (int i = 0; i < 4; i++)
#pragma unroll
                for (int j = 0; j < 8; j++)
                    acc[i][j] = fmaf(pf[i], vf[j], acc[i][j]);
        }
    }

#pragma unroll
    for (int i = 0; i < 4; i++) {
        const float inv = 1.0f / l_i[i];
        const int srow = q0 + i * 16 + ty;
        __half* op = gout + (rowbase + srow) * DMODEL + coloff;
#pragma unroll
        for (int j = 0; j < 8; j++)
            op[j * 8 + tx] = __float2half_rn(acc[i][j] * inv);
    }
}

// ============================================================================
// launch
// ============================================================================
extern "C" void kernel_launch(void* const* d_in, const int* in_sizes, int n_in,
                              void* d_out, int out_size)
{
    const float* Q   = (const float*)d_in[0];
    const float* K   = (const float*)d_in[1];
    const float* V   = (const float*)d_in[2];
    // d_in[3] = mask (causal tril; handled analytically)
    const float* W_q = (const float*)d_in[4];
    const float* b_q = (const float*)d_in[5];
    const float* W_k = (const float*)d_in[6];
    const float* b_k = (const float*)d_in[7];
    const float* W_v = (const float*)d_in[8];
    const float* b_v = (const float*)d_in[9];
    const float* W_o = (const float*)d_in[10];
    const float* b_o = (const float*)d_in[11];
    float* out = (float*)d_out;

    float  *gq, *gk, *gv;
    __half *gattn, *hq, *hk, *hv, *hw;
    cudaGetSymbolAddress((void**)&gq,    g_q);
    cudaGetSymbolAddress((void**)&gk,    g_k);
    cudaGetSymbolAddress((void**)&gv,    g_v);
    cudaGetSymbolAddress((void**)&gattn, g_attn);
    cudaGetSymbolAddress((void**)&hq,    g_hq);
    cudaGetSymbolAddress((void**)&hk,    g_hk);
    cudaGetSymbolAddress((void**)&hv,    g_hv);
    cudaGetSymbolAddress((void**)&hw,    g_hw);

    cudaFuncSetAttribute(flash_kernel,
                         cudaFuncAttributeMaxDynamicSharedMemorySize, FLASH_SMEM);

    const int nBig = MM * DMODEL;          // 8,388,608
    const int nW   = DMODEL * DMODEL;      // 1,048,576

    f2h_kernel<<<nBig / 4 / 256, 256>>>(Q,   hq,                  nBig);
    f2h_kernel<<<nBig / 4 / 256, 256>>>(K,   hk,                  nBig);
    f2h_kernel<<<nBig / 4 / 256, 256>>>(V,   hv,                  nBig);
    f2h_kernel<<<nW   / 4 / 256, 256>>>(W_q, hw + 0 * (size_t)nW, nW);
    f2h_kernel<<<nW   / 4 / 256, 256>>>(W_k, hw + 1 * (size_t)nW, nW);
    f2h_kernel<<<nW   / 4 / 256, 256>>>(W_v, hw + 2 * (size_t)nW, nW);
    f2h_kernel<<<nW   / 4 / 256, 256>>>(W_o, hw + 3 * (size_t)nW, nW);

    dim3 ggrid(DMODEL / 128, MM / 128);    // (8, 64)

    gemm_hmma<<<ggrid, 256>>>(hq, hw + 0 * (size_t)nW, b_q, gq);
    gemm_hmma<<<ggrid, 256>>>(hk, hw + 1 * (size_t)nW, b_k, gk);
    gemm_hmma<<<ggrid, 256>>>(hv, hw + 2 * (size_t)nW, b_v, gv);

    flash_kernel<<<dim3(SS / FBM, BB * HH), 128, FLASH_SMEM>>>(gq, gk, gv, gattn);

    gemm_hmma<<<ggrid, 256>>>(gattn, hw + 3 * (size_t)nW, b_o, out);
}